// round 16
// baseline (speedup 1.0000x reference)
#include <cuda_runtime.h>
#include <cuda_bf16.h>
#include <math.h>
#include <stdint.h>

// Problem constants (fixed for this instance)
#define HID   512
#define NH    8
#define HD    64
#define BQ    2048   // query length
#define BB    2      // batch
#define SSQ   4096   // side length
#define TOPK  64
#define NEGV  (-1e9f)

// -------- scratch (device globals; no allocation) --------
__device__ float g_q[(size_t)BB * BQ * HID];     // 8 MB (exact fp32 q)
__device__ float g_k[(size_t)SSQ * HID];         // 8 MB (exact fp32 k)
__device__ float g_v[(size_t)SSQ * HID];         // 8 MB
__device__ float g_ctx[(size_t)BB * BQ * HID];   // 8 MB
__device__ __nv_bfloat16 g_sb[(size_t)BB * NH * BQ * SSQ];  // 256 MB bf16 raw scores
__device__ unsigned g_mbits[(size_t)BB * BQ * SSQ / 32];    // 2 MB bitmask
// plain bf16 copies of q and k (MMA error absorbed by guard band)
__device__ __nv_bfloat16 g_qh[(size_t)BB * BQ * HID];
__device__ __nv_bfloat16 g_kh[(size_t)SSQ * HID];

// ============================================================
// bf16 MMA (baseline PTX, sm_80+): D += A*B, m16n8k16, fp32 accum
// ============================================================
__device__ __forceinline__ void mma_bf16(float c[4],
                                         const uint32_t a[4],
                                         const uint32_t b[2]) {
    asm volatile(
        "mma.sync.aligned.m16n8k16.row.col.f32.bf16.bf16.f32 "
        "{%0,%1,%2,%3}, {%4,%5,%6,%7}, {%8,%9}, {%0,%1,%2,%3};"
        : "+f"(c[0]), "+f"(c[1]), "+f"(c[2]), "+f"(c[3])
        : "r"(a[0]), "r"(a[1]), "r"(a[2]), "r"(a[3]),
          "r"(b[0]), "r"(b[1]));
}

// ============================================================
// SGEMM: C[M,512] = A[M,512] @ W[512,512] + bias  (known good)
// ============================================================
__global__ void __launch_bounds__(256) sgemm_bias(
    const float* __restrict__ A, const float* __restrict__ W,
    const float* __restrict__ bias, float* __restrict__ C)
{
    __shared__ float As[16][132];
    __shared__ float Ws[16][132];

    const int tid = threadIdx.x;
    const int bm = blockIdx.y * 128;
    const int bn = blockIdx.x * 128;
    const int tm = tid >> 4;
    const int tn = tid & 15;

    float acc[8][8];
#pragma unroll
    for (int i = 0; i < 8; i++)
#pragma unroll
        for (int j = 0; j < 8; j++) acc[i][j] = 0.f;

    for (int k0 = 0; k0 < 512; k0 += 16) {
#pragma unroll
        for (int it = 0; it < 2; it++) {
            int l = tid + it * 256;
            int r = l >> 2;
            int c4 = (l & 3) * 4;
            float4 av = *(const float4*)(A + (size_t)(bm + r) * 512 + k0 + c4);
            As[c4 + 0][r] = av.x;
            As[c4 + 1][r] = av.y;
            As[c4 + 2][r] = av.z;
            As[c4 + 3][r] = av.w;
        }
#pragma unroll
        for (int it = 0; it < 2; it++) {
            int l = tid + it * 256;
            int kr = l >> 5;
            int c4 = (l & 31) * 4;
            *(float4*)&Ws[kr][c4] =
                *(const float4*)(W + (size_t)(k0 + kr) * 512 + bn + c4);
        }
        __syncthreads();

#pragma unroll
        for (int k = 0; k < 16; k++) {
            float ra[8], rb[8];
            *(float4*)&ra[0] = *(float4*)&As[k][tm * 4];
            *(float4*)&ra[4] = *(float4*)&As[k][64 + tm * 4];
            *(float4*)&rb[0] = *(float4*)&Ws[k][tn * 4];
            *(float4*)&rb[4] = *(float4*)&Ws[k][64 + tn * 4];
#pragma unroll
            for (int i = 0; i < 8; i++)
#pragma unroll
                for (int j = 0; j < 8; j++)
                    acc[i][j] = fmaf(ra[i], rb[j], acc[i][j]);
        }
        __syncthreads();
    }

#pragma unroll
    for (int i = 0; i < 8; i++) {
        int r = bm + ((i < 4) ? (tm * 4 + i) : (64 + tm * 4 + (i - 4)));
#pragma unroll
        for (int jj = 0; jj < 2; jj++) {
            int c = bn + jj * 64 + tn * 4;
            float4 o;
            o.x = acc[i][jj * 4 + 0] + bias[c + 0];
            o.y = acc[i][jj * 4 + 1] + bias[c + 1];
            o.z = acc[i][jj * 4 + 2] + bias[c + 2];
            o.w = acc[i][jj * 4 + 3] + bias[c + 3];
            *(float4*)(C + (size_t)r * 512 + c) = o;
        }
    }
}

// ============================================================
// fp32 -> plain bf16 (round-nearest)
// ============================================================
__global__ void __launch_bounds__(256) cvt_bf16(
    const float* __restrict__ src, __nv_bfloat16* __restrict__ dst, int n4)
{
    int i = blockIdx.x * 256 + threadIdx.x;
    if (i >= n4) return;
    float4 x = ((const float4*)src)[i];
    ((__nv_bfloat162*)dst)[i * 2 + 0] =
        __nv_bfloat162(__float2bfloat16(x.x), __float2bfloat16(x.y));
    ((__nv_bfloat162*)dst)[i * 2 + 1] =
        __nv_bfloat162(__float2bfloat16(x.z), __float2bfloat16(x.w));
}

// ============================================================
// mask int32 -> bitmask (one bit per (b,q,s)); 128MB -> 2MB
// ============================================================
__global__ void __launch_bounds__(256) maskbits_kernel(const int* __restrict__ mask)
{
    const int nwords = (BB * BQ * SSQ) / 32;   // 524288
    int warp = (blockIdx.x * blockDim.x + threadIdx.x) >> 5;
    int lane = threadIdx.x & 31;
    int nwarp = (gridDim.x * blockDim.x) >> 5;
    for (int w = warp; w < nwords; w += nwarp) {
        int m = mask[(size_t)w * 32 + lane];
        unsigned bits = __ballot_sync(0xFFFFFFFFu, m != 0);
        if (lane == 0) g_mbits[w] = bits;
    }
}

// ============================================================
// Scores via mma.sync bf16 (plain): one 128x128 tile per CTA.
// grid (32 st, 16 qt, 16 bh); stores raw scaled bf16 scores.
// Epilogue staged through smem for fully-coalesced 16B stores.
// ============================================================
#define TW         36                    // uint32 words per smem row
#define TILE_WORDS (128 * TW)            // 4608 words = 18,432 B
#define WBW        68                    // staging words per row (bank-safe, 16B-aligned)
#define SCORES_SMEM (2 * TILE_WORDS * 4) // 36,864 B (staging 128*68*4=34,816 fits)

__global__ void __launch_bounds__(256, 2) scores_mma()
{
    extern __shared__ uint32_t sm32[];
    uint32_t* Qt = sm32;
    uint32_t* Kt = sm32 + TILE_WORDS;

    const int tid = threadIdx.x;
    const int wid = tid >> 5;
    const int lid = tid & 31;
    const int g   = lid >> 2;      // groupID 0..7
    const int tig = lid & 3;       // thread-in-group 0..3
    const int wm  = wid & 1;       // 2 m-groups of 64 rows
    const int wn  = wid >> 1;      // 4 n-groups of 32 cols

    const int s0 = blockIdx.x * 128;
    const int q0 = blockIdx.y * 128;
    const int bh = blockIdx.z;     // 0..15
    const int b  = bh >> 3;
    const int h  = bh & 7;

    // ---- load Q and K tiles (plain bf16)
    {
        const uint4* srcq = (const uint4*)(g_qh + ((size_t)(b * BQ + q0)) * 512 + h * 64);
        const uint4* srck = (const uint4*)(g_kh + (size_t)s0 * 512 + h * 64);
        uint4* dq = (uint4*)Qt;
        uint4* dk = (uint4*)Kt;
#pragma unroll
        for (int it = 0; it < 4; it++) {
            int t = tid + it * 256;      // 0..1023
            int r = t >> 3;              // 0..127
            int c = t & 7;               // 0..7
            dq[r * 9 + c] = srcq[(size_t)r * 64 + c];
            dk[r * 9 + c] = srck[(size_t)r * 64 + c];
        }
    }
    __syncthreads();

    float acc[4][4][4];
#pragma unroll
    for (int mt = 0; mt < 4; mt++)
#pragma unroll
        for (int nt = 0; nt < 4; nt++)
#pragma unroll
            for (int e = 0; e < 4; e++) acc[mt][nt][e] = 0.f;

#pragma unroll
    for (int kc = 0; kc < 4; kc++) {
        const int kw = kc * 8;

        uint32_t bf_[4][2];
#pragma unroll
        for (int nt = 0; nt < 4; nt++) {
            const int nr = (wn * 32 + nt * 8 + g) * TW + kw + tig;
            bf_[nt][0] = Kt[nr];
            bf_[nt][1] = Kt[nr + 4];
        }

#pragma unroll
        for (int mt = 0; mt < 4; mt++) {
            const int r0 = (wm * 64 + mt * 16 + g) * TW + kw + tig;
            const int r8 = r0 + 8 * TW;
            uint32_t af_[4];
            af_[0] = Qt[r0];     af_[1] = Qt[r8];
            af_[2] = Qt[r0 + 4]; af_[3] = Qt[r8 + 4];

#pragma unroll
            for (int nt = 0; nt < 4; nt++) mma_bf16(acc[mt][nt], af_, bf_[nt]);
        }
    }

    // ---- epilogue: pack -> smem staging -> coalesced 16B stores
    __syncthreads();            // Qt/Kt dead; reuse smem as staging
    uint32_t* wb = sm32;        // 128 rows x WBW words (bf16x2 per word)

#pragma unroll
    for (int mt = 0; mt < 4; mt++) {
        const int qr0 = wm * 64 + mt * 16 + g;
#pragma unroll
        for (int nt = 0; nt < 4; nt++) {
            const int cw = wn * 16 + nt * 4 + tig;   // word col (2 bf16 per word)
            __nv_bfloat162 p0(__float2bfloat16(acc[mt][nt][0] * 0.125f),
                              __float2bfloat16(acc[mt][nt][1] * 0.125f));
            __nv_bfloat162 p1(__float2bfloat16(acc[mt][nt][2] * 0.125f),
                              __float2bfloat16(acc[mt][nt][3] * 0.125f));
            wb[qr0 * WBW + cw]       = *(uint32_t*)&p0;
            wb[(qr0 + 8) * WBW + cw] = *(uint32_t*)&p1;
        }
    }
    __syncthreads();

    __nv_bfloat16* srow0 = g_sb + ((size_t)bh * BQ + q0) * SSQ + s0;
#pragma unroll
    for (int it = 0; it < 8; it++) {
        int t = tid + it * 256;          // 0..2047
        int r = t >> 4;                  // 0..127
        int c = t & 15;                  // uint4 index within row
        uint4 v = *(uint4*)&wb[r * WBW + c * 4];
        *(uint4*)(srow0 + (size_t)r * SSQ + c * 8) = v;
    }
}

// ============================================================
// Top-k: masked bf16 keys; 2-pass radix with warp-shuffle scans;
// abs+rel guard band; exact fp32 recompute via coalesced smem
// staging (sequential-k order); exact ranking; softmax; ctx.
// ============================================================
#define CAND_CAP 256
#define SEL_CAP  128
#define KSPAD 68   // row stride in floats: 68*4=272 B, 16B-aligned rows

__global__ void __launch_bounds__(256) topk_ctx_kernel()
{
    const size_t row = blockIdx.x;          // ((b*8+h)*2048 + q)
    const int q = (int)(row & 2047);
    const int bh = (int)(row >> 11);
    const int h = bh & 7;
    const int b = bh >> 3;

    const __nv_bfloat16* srow = g_sb + row * SSQ;
    const int tid = threadIdx.x;
    const int lane = tid & 31;
    const int warp = tid >> 5;

    __shared__ float red[256];
    __shared__ unsigned hist[256];
    __shared__ unsigned wsum[8];
    __shared__ unsigned mrow[128];          // 4096-bit mask row
    __shared__ unsigned sh_hi, sh_want, sh_T;
    __shared__ int nc, cnt;
    __shared__ int   Bidx[CAND_CAP];
    __shared__ float Bex[CAND_CAP];
    __shared__ int   sidx[SEL_CAP];
    __shared__ float sval[SEL_CAP];
    __shared__ float sp[SEL_CAP];
    __shared__ float ctxs[4][64];
    __shared__ float qv[64];
    __shared__ __align__(16) float ks[64][KSPAD];  // staged candidate k-rows

    // preload exact q row (fp32) + mask bits for this (b,q)
    if (tid < 64)
        qv[tid] = g_q[((size_t)(b * BQ + q)) * 512 + h * HD + tid];
    if (tid < 128)
        mrow[tid] = g_mbits[((size_t)(b * BQ + q)) * 128 + tid];
    if (tid == 0) { nc = 0; cnt = 0; }
    __syncthreads();

    // ---- load 16 bf16 scores per thread; key = unmasked ? flip : 0
    unsigned u[16];
    {
        uint4 r0 = ((const uint4*)srow)[tid * 2];
        uint4 r1 = ((const uint4*)srow)[tid * 2 + 1];
        unsigned w[8] = {r0.x, r0.y, r0.z, r0.w, r1.x, r1.y, r1.z, r1.w};
        const unsigned bits16 = mrow[tid >> 1] >> ((tid & 1) * 16);
#pragma unroll
        for (int j = 0; j < 8; j++) {
            unsigned lo = w[j] & 0xFFFFu, hi = w[j] >> 16;
            unsigned klo = (lo & 0x8000u) ? (~lo & 0xFFFFu) : (lo | 0x8000u);
            unsigned khi = (hi & 0x8000u) ? (~hi & 0xFFFFu) : (hi | 0x8000u);
            u[2 * j]     = ((bits16 >> (2 * j))     & 1u) ? klo : 0u;
            u[2 * j + 1] = ((bits16 >> (2 * j + 1)) & 1u) ? khi : 0u;
        }
    }

    // ---- radix pass 1: high byte (warp-shuffle scan) ----
    hist[tid] = 0u;
    __syncthreads();
#pragma unroll
    for (int i = 0; i < 16; i++) atomicAdd(&hist[u[i] >> 8], 1u);
    __syncthreads();
    {
        const unsigned v = hist[255 - tid];   // descending key order
        unsigned x = v;
#pragma unroll
        for (int o = 1; o < 32; o <<= 1) {
            unsigned t = __shfl_up_sync(0xFFFFFFFFu, x, o);
            if (lane >= o) x += t;
        }
        if (lane == 31) wsum[warp] = x;
        __syncthreads();
        unsigned off = 0;
#pragma unroll
        for (int w = 0; w < 8; w++) off += (w < warp) ? wsum[w] : 0u;
        const unsigned cum = x + off;
        const unsigned prev = cum - v;
        if (cum >= TOPK && prev < TOPK) { sh_hi = 255u - tid; sh_want = TOPK - prev; }
        __syncthreads();
    }
    const unsigned hi8 = sh_hi, want2 = sh_want;

    // ---- radix pass 2: low byte within hi8 (warp-shuffle scan) ----
    hist[tid] = 0u;
    __syncthreads();
#pragma unroll
    for (int i = 0; i < 16; i++)
        if ((u[i] >> 8) == hi8) atomicAdd(&hist[u[i] & 255u], 1u);
    __syncthreads();
    {
        const unsigned v = hist[255 - tid];
        unsigned x = v;
#pragma unroll
        for (int o = 1; o < 32; o <<= 1) {
            unsigned t = __shfl_up_sync(0xFFFFFFFFu, x, o);
            if (lane >= o) x += t;
        }
        if (lane == 31) wsum[warp] = x;
        __syncthreads();
        unsigned off = 0;
#pragma unroll
        for (int w = 0; w < 8; w++) off += (w < warp) ? wsum[w] : 0u;
        const unsigned cum = x + off;
        const unsigned prev = cum - v;
        if (cum >= want2 && prev < want2) sh_T = (hi8 << 8) | (255u - tid);
        __syncthreads();
    }

    // ---- guard band: absolute + relative (covers bf16 quant + MMA error)
    int Tlo;
    {
        unsigned kT = sh_T;
        unsigned b16 = (kT & 0x8000u) ? (kT & 0x7FFFu) : ((~kT) & 0xFFFFu);
        float tval = __uint_as_float(b16 << 16);
        float gband = 0.006f + 0.012f * fabsf(tval);
        __nv_bfloat16 tb = __float2bfloat16_rd(tval - gband);
        unsigned tbits = *reinterpret_cast<unsigned short*>(&tb);
        unsigned klo = (tbits & 0x8000u) ? ((~tbits) & 0xFFFFu) : (tbits | 0x8000u);
        Tlo = (int)klo - 1;
        if (Tlo < 1) Tlo = 1;               // key 0 = masked, never a candidate
    }

    // ---- candidates
#pragma unroll
    for (int i = 0; i < 16; i++) {
        if ((int)u[i] >= Tlo) {
            int pos = atomicAdd(&nc, 1);
            if (pos < CAND_CAP) Bidx[pos] = tid * 16 + i;
        }
    }
    __syncthreads();
    const int nb = (nc < CAND_CAP) ? nc : CAND_CAP;

    // ---- exact fp32 recompute via coalesced smem staging
    //      (sequential-k accumulation order preserved exactly)
    for (int base = 0; base < nb; base += 64) {
        const int chunk = (nb - base < 64) ? (nb - base) : 64;
        __syncthreads();
        {
            const int rr = tid >> 2;        // 0..63
            const int part = tid & 3;
            if (rr < chunk) {
                const float4* kr = (const float4*)
                    (g_k + (size_t)Bidx[base + rr] * 512 + h * HD);
                float* dst = &ks[rr][part * 16];
                float4 v0 = kr[part * 4 + 0];
                float4 v1 = kr[part * 4 + 1];
                float4 v2 = kr[part * 4 + 2];
                float4 v3 = kr[part * 4 + 3];
                *(float4*)(dst + 0)  = v0;
                *(float4*)(dst + 4)  = v1;
                *(float4*)(dst + 8)  = v2;
                *(float4*)(dst + 12) = v3;
            }
        }
        __syncthreads();
        if (tid < chunk) {
            float a = 0.f;
#pragma unroll
            for (int d = 0; d < 64; d++) a = fmaf(qv[d], ks[tid][d], a);
            Bex[base + tid] = a * 0.125f;
        }
    }
    __syncthreads();

    // ---- exact ranking: keep if (#strictly greater) < 64 (>= tie semantics)
    if (tid < nb) {
        const float s = Bex[tid];
        int greater = 0;
        for (int j = 0; j < nb; j++) greater += (Bex[j] > s) ? 1 : 0;
        if (greater < TOPK) {
            int pos = atomicAdd(&cnt, 1);
            if (pos < SEL_CAP) { sidx[pos] = Bidx[tid]; sval[pos] = s; }
        }
    }
    __syncthreads();
    const int ns = (cnt < SEL_CAP) ? cnt : SEL_CAP;

    // ---- rowmax over selected (exact)
    red[tid] = (tid < ns) ? sval[tid] : -INFINITY;
    __syncthreads();
    for (int o = 128; o > 0; o >>= 1) {
        if (tid < o) red[tid] = fmaxf(red[tid], red[tid + o]);
        __syncthreads();
    }
    const float rowmax = red[0];
    __syncthreads();

    // ---- probs + sum
    float p = 0.f;
    if (tid < ns) { p = expf(sval[tid] - rowmax); sp[tid] = p; }
    red[tid] = p;
    __syncthreads();
    for (int o = 128; o > 0; o >>= 1) {
        if (tid < o) red[tid] += red[tid + o];
        __syncthreads();
    }
    const float invd = 1.0f / red[0];

    // ---- ctx = sum_sel p * v[s, h, :]
    const int gg = tid >> 6;
    const int d = tid & 63;
    const float* vh = g_v + h * HD;
    float a = 0.f;
    for (int e = gg; e < ns; e += 4)
        a += sp[e] * vh[(size_t)sidx[e] * 512 + d];
    ctxs[gg][d] = a;
    __syncthreads();

    if (tid < 64) {
        float r2 = (ctxs[0][tid] + ctxs[1][tid] + ctxs[2][tid] + ctxs[3][tid]) * invd;
        g_ctx[((size_t)(b * BQ + q)) * 512 + h * HD + tid] = r2;
    }
}

// ============================================================
// host launcher — ordered so ncu (-s 5 -c 1) captures scores_mma
// ============================================================
extern "C" void kernel_launch(void* const* d_in, const int* in_sizes, int n_in,
                              void* d_out, int out_size)
{
    const float* main_in = (const float*)d_in[0];
    const float* side_in = (const float*)d_in[1];
    const int*   mask    = (const int*)d_in[2];
    const float* Wq = (const float*)d_in[3];
    const float* bq = (const float*)d_in[4];
    const float* Wk = (const float*)d_in[5];
    const float* bk = (const float*)d_in[6];
    const float* Wv = (const float*)d_in[7];
    const float* bv = (const float*)d_in[8];
    const float* Wo = (const float*)d_in[9];
    const float* bo = (const float*)d_in[10];
    float* out = (float*)d_out;

    float *pq, *pk, *pv, *pctx;
    cudaGetSymbolAddress((void**)&pq, g_q);
    cudaGetSymbolAddress((void**)&pk, g_k);
    cudaGetSymbolAddress((void**)&pv, g_v);
    cudaGetSymbolAddress((void**)&pctx, g_ctx);
    __nv_bfloat16 *pqh, *pkh;
    cudaGetSymbolAddress((void**)&pqh, g_qh);
    cudaGetSymbolAddress((void**)&pkh, g_kh);

    cudaFuncSetAttribute(scores_mma, cudaFuncAttributeMaxDynamicSharedMemorySize,
                         SCORES_SMEM);

    dim3 gB(512 / 128, (BB * BQ) / 128);   // (4, 32)

    // launch 1: mask -> bitmask (independent)
    maskbits_kernel<<<1024, 256>>>(mask);

    // launches 2-3: q and k projections (fp32 exact)
    sgemm_bias<<<gB, 256>>>(main_in, Wq, bq, pq);
    sgemm_bias<<<gB, 256>>>(side_in, Wk, bk, pk);

    // launches 4-5: bf16 copies of q and k
    cvt_bf16<<<((BB * BQ * HID) / 4 + 255) / 256, 256>>>(pq, pqh, (BB * BQ * HID) / 4);
    cvt_bf16<<<((SSQ * HID) / 4 + 255) / 256, 256>>>(pk, pkh, (SSQ * HID) / 4);

    // launch 6 (ncu capture target): raw scaled bf16 scores
    scores_mma<<<dim3(SSQ / 128, BQ / 128, BB * NH), 256, SCORES_SMEM>>>();

    // launch 7: v projection (only needed by topk)
    sgemm_bias<<<gB, 256>>>(side_in, Wv, bv, pv);

    // launch 8: top-64 + exact recompute + softmax + ctx
    topk_ctx_kernel<<<BB * NH * BQ, 256>>>();

    // launch 9: output projection
    sgemm_bias<<<gB, 256>>>(pctx, Wo, bo, out);
}

// round 17
// speedup vs baseline: 1.0186x; 1.0186x over previous
#include <cuda_runtime.h>
#include <cuda_bf16.h>
#include <math.h>
#include <stdint.h>

// Problem constants (fixed for this instance)
#define HID   512
#define NH    8
#define HD    64
#define BQ    2048   // query length
#define BB    2      // batch
#define SSQ   4096   // side length
#define TOPK  64
#define NEGV  (-1e9f)

// -------- scratch (device globals; no allocation) --------
__device__ float g_q[(size_t)BB * BQ * HID];     // 8 MB (exact fp32 q)
__device__ float g_k[(size_t)SSQ * HID];         // 8 MB (exact fp32 k)
__device__ float g_v[(size_t)SSQ * HID];         // 8 MB
__device__ float g_ctx[(size_t)BB * BQ * HID];   // 8 MB
__device__ __nv_bfloat16 g_sb[(size_t)BB * NH * BQ * SSQ];  // 256 MB bf16 raw scores
__device__ unsigned g_mbits[(size_t)BB * BQ * SSQ / 32];    // 2 MB bitmask
// plain bf16 copies of q and k (MMA error absorbed by guard band)
__device__ __nv_bfloat16 g_qh[(size_t)BB * BQ * HID];
__device__ __nv_bfloat16 g_kh[(size_t)SSQ * HID];

// ============================================================
// bf16 MMA (baseline PTX, sm_80+): D += A*B, m16n8k16, fp32 accum
// ============================================================
__device__ __forceinline__ void mma_bf16(float c[4],
                                         const uint32_t a[4],
                                         const uint32_t b[2]) {
    asm volatile(
        "mma.sync.aligned.m16n8k16.row.col.f32.bf16.bf16.f32 "
        "{%0,%1,%2,%3}, {%4,%5,%6,%7}, {%8,%9}, {%0,%1,%2,%3};"
        : "+f"(c[0]), "+f"(c[1]), "+f"(c[2]), "+f"(c[3])
        : "r"(a[0]), "r"(a[1]), "r"(a[2]), "r"(a[3]),
          "r"(b[0]), "r"(b[1]));
}

// ============================================================
// SGEMM (64x128 tile, 4x8 microtile): C[M,512] = A @ W + bias
// grid (4, M/64); 256 threads; higher occupancy than 128x128.
// Same load/compute/store structure as the verified 128x128 kernel.
// ============================================================
__global__ void __launch_bounds__(256) sgemm_bias64(
    const float* __restrict__ A, const float* __restrict__ W,
    const float* __restrict__ bias, float* __restrict__ C)
{
    __shared__ float As[16][68];    // 64 rows, transposed, +4 pad
    __shared__ float Ws[16][132];   // 128 cols, +4 pad

    const int tid = threadIdx.x;
    const int bm = blockIdx.y * 64;
    const int bn = blockIdx.x * 128;
    const int tm = tid >> 4;        // 0..15 (rows of 4)
    const int tn = tid & 15;        // 0..15 (cols of 4, x2 chunks)

    float acc[4][8];
#pragma unroll
    for (int i = 0; i < 4; i++)
#pragma unroll
        for (int j = 0; j < 8; j++) acc[i][j] = 0.f;

    for (int k0 = 0; k0 < 512; k0 += 16) {
        // A tile: 64 rows x 16 k = 256 float4, 1 iter
        {
            int r = tid >> 2;              // 0..63
            int c4 = (tid & 3) * 4;        // 0,4,8,12
            float4 av = *(const float4*)(A + (size_t)(bm + r) * 512 + k0 + c4);
            As[c4 + 0][r] = av.x;
            As[c4 + 1][r] = av.y;
            As[c4 + 2][r] = av.z;
            As[c4 + 3][r] = av.w;
        }
        // W tile: 16 k x 128 n = 512 float4, 2 iters
#pragma unroll
        for (int it = 0; it < 2; it++) {
            int l = tid + it * 256;
            int kr = l >> 5;               // 0..15
            int c4 = (l & 31) * 4;         // 0..124
            *(float4*)&Ws[kr][c4] =
                *(const float4*)(W + (size_t)(k0 + kr) * 512 + bn + c4);
        }
        __syncthreads();

#pragma unroll
        for (int k = 0; k < 16; k++) {
            float ra[4], rb[8];
            *(float4*)&ra[0] = *(float4*)&As[k][tm * 4];
            *(float4*)&rb[0] = *(float4*)&Ws[k][tn * 4];
            *(float4*)&rb[4] = *(float4*)&Ws[k][64 + tn * 4];
#pragma unroll
            for (int i = 0; i < 4; i++)
#pragma unroll
                for (int j = 0; j < 8; j++)
                    acc[i][j] = fmaf(ra[i], rb[j], acc[i][j]);
        }
        __syncthreads();
    }

#pragma unroll
    for (int i = 0; i < 4; i++) {
        int r = bm + tm * 4 + i;
#pragma unroll
        for (int jj = 0; jj < 2; jj++) {
            int c = bn + jj * 64 + tn * 4;
            float4 o;
            o.x = acc[i][jj * 4 + 0] + bias[c + 0];
            o.y = acc[i][jj * 4 + 1] + bias[c + 1];
            o.z = acc[i][jj * 4 + 2] + bias[c + 2];
            o.w = acc[i][jj * 4 + 3] + bias[c + 3];
            *(float4*)(C + (size_t)r * 512 + c) = o;
        }
    }
}

// ============================================================
// fp32 -> plain bf16 (round-nearest)
// ============================================================
__global__ void __launch_bounds__(256) cvt_bf16(
    const float* __restrict__ src, __nv_bfloat16* __restrict__ dst, int n4)
{
    int i = blockIdx.x * 256 + threadIdx.x;
    if (i >= n4) return;
    float4 x = ((const float4*)src)[i];
    ((__nv_bfloat162*)dst)[i * 2 + 0] =
        __nv_bfloat162(__float2bfloat16(x.x), __float2bfloat16(x.y));
    ((__nv_bfloat162*)dst)[i * 2 + 1] =
        __nv_bfloat162(__float2bfloat16(x.z), __float2bfloat16(x.w));
}

// ============================================================
// mask int32 -> bitmask (one bit per (b,q,s)); 128MB -> 2MB
// ============================================================
__global__ void __launch_bounds__(256) maskbits_kernel(const int* __restrict__ mask)
{
    const int nwords = (BB * BQ * SSQ) / 32;   // 524288
    int warp = (blockIdx.x * blockDim.x + threadIdx.x) >> 5;
    int lane = threadIdx.x & 31;
    int nwarp = (gridDim.x * blockDim.x) >> 5;
    for (int w = warp; w < nwords; w += nwarp) {
        int m = mask[(size_t)w * 32 + lane];
        unsigned bits = __ballot_sync(0xFFFFFFFFu, m != 0);
        if (lane == 0) g_mbits[w] = bits;
    }
}

// ============================================================
// Scores via mma.sync bf16: TWO 128x128 s-tiles per CTA
// (Q tile loaded once, reused). grid (16 st2, 16 qt, 16 bh).
// Direct-store epilogue (R15-verified pattern).
// ============================================================
#define TW         36                    // uint32 words per smem row
#define TILE_WORDS (128 * TW)            // 4608 words = 18,432 B
#define SCORES_SMEM (2 * TILE_WORDS * 4) // 36,864 B

__global__ void __launch_bounds__(256, 2) scores_mma()
{
    extern __shared__ uint32_t sm32[];
    uint32_t* Qt = sm32;
    uint32_t* Kt = sm32 + TILE_WORDS;

    const int tid = threadIdx.x;
    const int wid = tid >> 5;
    const int lid = tid & 31;
    const int g   = lid >> 2;      // groupID 0..7
    const int tig = lid & 3;       // thread-in-group 0..3
    const int wm  = wid & 1;       // 2 m-groups of 64 rows
    const int wn  = wid >> 1;      // 4 n-groups of 32 cols

    const int q0 = blockIdx.y * 128;
    const int bh = blockIdx.z;     // 0..15
    const int b  = bh >> 3;
    const int h  = bh & 7;

    // ---- load Q tile once (reused for both s-tiles)
    {
        const uint4* srcq = (const uint4*)(g_qh + ((size_t)(b * BQ + q0)) * 512 + h * 64);
        uint4* dq = (uint4*)Qt;
#pragma unroll
        for (int it = 0; it < 4; it++) {
            int t = tid + it * 256;      // 0..1023
            int r = t >> 3;              // 0..127
            int c = t & 7;               // 0..7
            dq[r * 9 + c] = srcq[(size_t)r * 64 + c];
        }
    }

    __nv_bfloat16* srow0 = g_sb + ((size_t)bh * BQ + q0) * SSQ;

#pragma unroll
    for (int st2 = 0; st2 < 2; st2++) {
        const int s0 = blockIdx.x * 256 + st2 * 128;

        __syncthreads();   // Q stores visible (iter0); prior MMA Kt reads done (iter1)
        {
            const uint4* srck = (const uint4*)(g_kh + (size_t)s0 * 512 + h * 64);
            uint4* dk = (uint4*)Kt;
#pragma unroll
            for (int it = 0; it < 4; it++) {
                int t = tid + it * 256;
                int r = t >> 3;
                int c = t & 7;
                dk[r * 9 + c] = srck[(size_t)r * 64 + c];
            }
        }
        __syncthreads();

        float acc[4][4][4];
#pragma unroll
        for (int mt = 0; mt < 4; mt++)
#pragma unroll
            for (int nt = 0; nt < 4; nt++)
#pragma unroll
                for (int e = 0; e < 4; e++) acc[mt][nt][e] = 0.f;

#pragma unroll
        for (int kc = 0; kc < 4; kc++) {
            const int kw = kc * 8;

            uint32_t bf_[4][2];
#pragma unroll
            for (int nt = 0; nt < 4; nt++) {
                const int nr = (wn * 32 + nt * 8 + g) * TW + kw + tig;
                bf_[nt][0] = Kt[nr];
                bf_[nt][1] = Kt[nr + 4];
            }

#pragma unroll
            for (int mt = 0; mt < 4; mt++) {
                const int r0 = (wm * 64 + mt * 16 + g) * TW + kw + tig;
                const int r8 = r0 + 8 * TW;
                uint32_t af_[4];
                af_[0] = Qt[r0];     af_[1] = Qt[r8];
                af_[2] = Qt[r0 + 4]; af_[3] = Qt[r8 + 4];

#pragma unroll
                for (int nt = 0; nt < 4; nt++) mma_bf16(acc[mt][nt], af_, bf_[nt]);
            }
        }

        // ---- epilogue: scale + bf16 store (direct, verified)
#pragma unroll
        for (int mt = 0; mt < 4; mt++) {
            const int qr0 = wm * 64 + mt * 16 + g;
#pragma unroll
            for (int nt = 0; nt < 4; nt++) {
                const int col = s0 + wn * 32 + nt * 8 + tig * 2;
                *(__nv_bfloat162*)(srow0 + (size_t)qr0 * SSQ + col) =
                    __nv_bfloat162(__float2bfloat16(acc[mt][nt][0] * 0.125f),
                                   __float2bfloat16(acc[mt][nt][1] * 0.125f));
                *(__nv_bfloat162*)(srow0 + (size_t)(qr0 + 8) * SSQ + col) =
                    __nv_bfloat162(__float2bfloat16(acc[mt][nt][2] * 0.125f),
                                   __float2bfloat16(acc[mt][nt][3] * 0.125f));
            }
        }
    }
}

// ============================================================
// Top-k: masked bf16 keys; 2-pass radix with warp-shuffle scans;
// abs+rel guard band; exact fp32 recompute via coalesced smem
// staging (sequential-k order); exact ranking; softmax; ctx.
// (byte-identical to the verified 884.7us build)
// ============================================================
#define CAND_CAP 256
#define SEL_CAP  128
#define KSPAD 68   // row stride in floats: 68*4=272 B, 16B-aligned rows

__global__ void __launch_bounds__(256) topk_ctx_kernel()
{
    const size_t row = blockIdx.x;          // ((b*8+h)*2048 + q)
    const int q = (int)(row & 2047);
    const int bh = (int)(row >> 11);
    const int h = bh & 7;
    const int b = bh >> 3;

    const __nv_bfloat16* srow = g_sb + row * SSQ;
    const int tid = threadIdx.x;
    const int lane = tid & 31;
    const int warp = tid >> 5;

    __shared__ float red[256];
    __shared__ unsigned hist[256];
    __shared__ unsigned wsum[8];
    __shared__ unsigned mrow[128];          // 4096-bit mask row
    __shared__ unsigned sh_hi, sh_want, sh_T;
    __shared__ int nc, cnt;
    __shared__ int   Bidx[CAND_CAP];
    __shared__ float Bex[CAND_CAP];
    __shared__ int   sidx[SEL_CAP];
    __shared__ float sval[SEL_CAP];
    __shared__ float sp[SEL_CAP];
    __shared__ float ctxs[4][64];
    __shared__ float qv[64];
    __shared__ __align__(16) float ks[64][KSPAD];  // staged candidate k-rows

    // preload exact q row (fp32) + mask bits for this (b,q)
    if (tid < 64)
        qv[tid] = g_q[((size_t)(b * BQ + q)) * 512 + h * HD + tid];
    if (tid < 128)
        mrow[tid] = g_mbits[((size_t)(b * BQ + q)) * 128 + tid];
    if (tid == 0) { nc = 0; cnt = 0; }
    __syncthreads();

    // ---- load 16 bf16 scores per thread; key = unmasked ? flip : 0
    unsigned u[16];
    {
        uint4 r0 = ((const uint4*)srow)[tid * 2];
        uint4 r1 = ((const uint4*)srow)[tid * 2 + 1];
        unsigned w[8] = {r0.x, r0.y, r0.z, r0.w, r1.x, r1.y, r1.z, r1.w};
        const unsigned bits16 = mrow[tid >> 1] >> ((tid & 1) * 16);
#pragma unroll
        for (int j = 0; j < 8; j++) {
            unsigned lo = w[j] & 0xFFFFu, hi = w[j] >> 16;
            unsigned klo = (lo & 0x8000u) ? (~lo & 0xFFFFu) : (lo | 0x8000u);
            unsigned khi = (hi & 0x8000u) ? (~hi & 0xFFFFu) : (hi | 0x8000u);
            u[2 * j]     = ((bits16 >> (2 * j))     & 1u) ? klo : 0u;
            u[2 * j + 1] = ((bits16 >> (2 * j + 1)) & 1u) ? khi : 0u;
        }
    }

    // ---- radix pass 1: high byte (warp-shuffle scan) ----
    hist[tid] = 0u;
    __syncthreads();
#pragma unroll
    for (int i = 0; i < 16; i++) atomicAdd(&hist[u[i] >> 8], 1u);
    __syncthreads();
    {
        const unsigned v = hist[255 - tid];   // descending key order
        unsigned x = v;
#pragma unroll
        for (int o = 1; o < 32; o <<= 1) {
            unsigned t = __shfl_up_sync(0xFFFFFFFFu, x, o);
            if (lane >= o) x += t;
        }
        if (lane == 31) wsum[warp] = x;
        __syncthreads();
        unsigned off = 0;
#pragma unroll
        for (int w = 0; w < 8; w++) off += (w < warp) ? wsum[w] : 0u;
        const unsigned cum = x + off;
        const unsigned prev = cum - v;
        if (cum >= TOPK && prev < TOPK) { sh_hi = 255u - tid; sh_want = TOPK - prev; }
        __syncthreads();
    }
    const unsigned hi8 = sh_hi, want2 = sh_want;

    // ---- radix pass 2: low byte within hi8 (warp-shuffle scan) ----
    hist[tid] = 0u;
    __syncthreads();
#pragma unroll
    for (int i = 0; i < 16; i++)
        if ((u[i] >> 8) == hi8) atomicAdd(&hist[u[i] & 255u], 1u);
    __syncthreads();
    {
        const unsigned v = hist[255 - tid];
        unsigned x = v;
#pragma unroll
        for (int o = 1; o < 32; o <<= 1) {
            unsigned t = __shfl_up_sync(0xFFFFFFFFu, x, o);
            if (lane >= o) x += t;
        }
        if (lane == 31) wsum[warp] = x;
        __syncthreads();
        unsigned off = 0;
#pragma unroll
        for (int w = 0; w < 8; w++) off += (w < warp) ? wsum[w] : 0u;
        const unsigned cum = x + off;
        const unsigned prev = cum - v;
        if (cum >= want2 && prev < want2) sh_T = (hi8 << 8) | (255u - tid);
        __syncthreads();
    }

    // ---- guard band: absolute + relative (covers bf16 quant + MMA error)
    int Tlo;
    {
        unsigned kT = sh_T;
        unsigned b16 = (kT & 0x8000u) ? (kT & 0x7FFFu) : ((~kT) & 0xFFFFu);
        float tval = __uint_as_float(b16 << 16);
        float gband = 0.006f + 0.012f * fabsf(tval);
        __nv_bfloat16 tb = __float2bfloat16_rd(tval - gband);
        unsigned tbits = *reinterpret_cast<unsigned short*>(&tb);
        unsigned klo = (tbits & 0x8000u) ? ((~tbits) & 0xFFFFu) : (tbits | 0x8000u);
        Tlo = (int)klo - 1;
        if (Tlo < 1) Tlo = 1;               // key 0 = masked, never a candidate
    }

    // ---- candidates
#pragma unroll
    for (int i = 0; i < 16; i++) {
        if ((int)u[i] >= Tlo) {
            int pos = atomicAdd(&nc, 1);
            if (pos < CAND_CAP) Bidx[pos] = tid * 16 + i;
        }
    }
    __syncthreads();
    const int nb = (nc < CAND_CAP) ? nc : CAND_CAP;

    // ---- exact fp32 recompute via coalesced smem staging
    //      (sequential-k accumulation order preserved exactly)
    for (int base = 0; base < nb; base += 64) {
        const int chunk = (nb - base < 64) ? (nb - base) : 64;
        __syncthreads();
        {
            const int rr = tid >> 2;        // 0..63
            const int part = tid & 3;
            if (rr < chunk) {
                const float4* kr = (const float4*)
                    (g_k + (size_t)Bidx[base + rr] * 512 + h * HD);
                float* dst = &ks[rr][part * 16];
                float4 v0 = kr[part * 4 + 0];
                float4 v1 = kr[part * 4 + 1];
                float4 v2 = kr[part * 4 + 2];
                float4 v3 = kr[part * 4 + 3];
                *(float4*)(dst + 0)  = v0;
                *(float4*)(dst + 4)  = v1;
                *(float4*)(dst + 8)  = v2;
                *(float4*)(dst + 12) = v3;
            }
        }
        __syncthreads();
        if (tid < chunk) {
            float a = 0.f;
#pragma unroll
            for (int d = 0; d < 64; d++) a = fmaf(qv[d], ks[tid][d], a);
            Bex[base + tid] = a * 0.125f;
        }
    }
    __syncthreads();

    // ---- exact ranking: keep if (#strictly greater) < 64 (>= tie semantics)
    if (tid < nb) {
        const float s = Bex[tid];
        int greater = 0;
        for (int j = 0; j < nb; j++) greater += (Bex[j] > s) ? 1 : 0;
        if (greater < TOPK) {
            int pos = atomicAdd(&cnt, 1);
            if (pos < SEL_CAP) { sidx[pos] = Bidx[tid]; sval[pos] = s; }
        }
    }
    __syncthreads();
    const int ns = (cnt < SEL_CAP) ? cnt : SEL_CAP;

    // ---- rowmax over selected (exact)
    red[tid] = (tid < ns) ? sval[tid] : -INFINITY;
    __syncthreads();
    for (int o = 128; o > 0; o >>= 1) {
        if (tid < o) red[tid] = fmaxf(red[tid], red[tid + o]);
        __syncthreads();
    }
    const float rowmax = red[0];
    __syncthreads();

    // ---- probs + sum
    float p = 0.f;
    if (tid < ns) { p = expf(sval[tid] - rowmax); sp[tid] = p; }
    red[tid] = p;
    __syncthreads();
    for (int o = 128; o > 0; o >>= 1) {
        if (tid < o) red[tid] += red[tid + o];
        __syncthreads();
    }
    const float invd = 1.0f / red[0];

    // ---- ctx = sum_sel p * v[s, h, :]
    const int gg = tid >> 6;
    const int d = tid & 63;
    const float* vh = g_v + h * HD;
    float a = 0.f;
    for (int e = gg; e < ns; e += 4)
        a += sp[e] * vh[(size_t)sidx[e] * 512 + d];
    ctxs[gg][d] = a;
    __syncthreads();

    if (tid < 64) {
        float r2 = (ctxs[0][tid] + ctxs[1][tid] + ctxs[2][tid] + ctxs[3][tid]) * invd;
        g_ctx[((size_t)(b * BQ + q)) * 512 + h * HD + tid] = r2;
    }
}

// ============================================================
// host launcher
// ============================================================
extern "C" void kernel_launch(void* const* d_in, const int* in_sizes, int n_in,
                              void* d_out, int out_size)
{
    const float* main_in = (const float*)d_in[0];
    const float* side_in = (const float*)d_in[1];
    const int*   mask    = (const int*)d_in[2];
    const float* Wq = (const float*)d_in[3];
    const float* bq = (const float*)d_in[4];
    const float* Wk = (const float*)d_in[5];
    const float* bk = (const float*)d_in[6];
    const float* Wv = (const float*)d_in[7];
    const float* bv = (const float*)d_in[8];
    const float* Wo = (const float*)d_in[9];
    const float* bo = (const float*)d_in[10];
    float* out = (float*)d_out;

    float *pq, *pk, *pv, *pctx;
    cudaGetSymbolAddress((void**)&pq, g_q);
    cudaGetSymbolAddress((void**)&pk, g_k);
    cudaGetSymbolAddress((void**)&pv, g_v);
    cudaGetSymbolAddress((void**)&pctx, g_ctx);
    __nv_bfloat16 *pqh, *pkh;
    cudaGetSymbolAddress((void**)&pqh, g_qh);
    cudaGetSymbolAddress((void**)&pkh, g_kh);

    cudaFuncSetAttribute(scores_mma, cudaFuncAttributeMaxDynamicSharedMemorySize,
                         SCORES_SMEM);

    dim3 gB64(512 / 128, (BB * BQ) / 64);   // (4, 64) for 64-row tiles

    // launch 1: mask -> bitmask (independent)
    maskbits_kernel<<<1024, 256>>>(mask);

    // launches 2-3: q and k projections (fp32 exact, higher-occupancy tiles)
    sgemm_bias64<<<gB64, 256>>>(main_in, Wq, bq, pq);
    sgemm_bias64<<<gB64, 256>>>(side_in, Wk, bk, pk);

    // launches 4-5: bf16 copies of q and k
    cvt_bf16<<<((BB * BQ * HID) / 4 + 255) / 256, 256>>>(pq, pqh, (BB * BQ * HID) / 4);
    cvt_bf16<<<((SSQ * HID) / 4 + 255) / 256, 256>>>(pk, pkh, (SSQ * HID) / 4);

    // launch 6: raw scaled bf16 scores (2 s-tiles per CTA)
    scores_mma<<<dim3(SSQ / 256, BQ / 128, BB * NH), 256, SCORES_SMEM>>>();

    // launch 7: v projection (only needed by topk)
    sgemm_bias64<<<gB64, 256>>>(side_in, Wv, bv, pv);

    // launch 8: top-64 + exact recompute + softmax + ctx
    topk_ctx_kernel<<<BB * NH * BQ, 256>>>();

    // launch 9: output projection
    sgemm_bias64<<<gB64, 256>>>(pctx, Wo, bo, out);
}